// round 1
// baseline (speedup 1.0000x reference)
#include <cuda_runtime.h>

#define BB 4
#define NN 16384
#define SSZ 2048            // queries per batch (NEVENT)
#define DD 62
#define CC 64               // D + 2
#define KK 64               // NSAMPLE
#define NQ (BB*SSZ)         // 8192 total queries
#define MMM 8388608         // SSZ*KK*CC per batch
#define R2 0.01f

// ---- scratch (device globals; fully overwritten every launch) ----
__device__ int   g_idx[NQ*KK];     // 2 MB neighbor indices
__device__ float g_mean[NQ*CC];    // 2 MB per-(query,channel) means
__device__ float g_ss[NQ];         // per-query sum of squared centered
__device__ float g_rstd[BB];       // 1/(std+1e-5) per batch

// ---------------------------------------------------------------------------
// K1: ball query. One warp per query. Ordered compaction of first 64 indices
// (ascending) with d^2 <= R^2, padded with the first hit. Early exit.
// Distance formula replicates reference fp32 op sequence exactly:
//   qn = qx*qx + qy*qy ; pn = px*px + py*py (mul,mul,add — no FMA)
//   c  = fma(qy,py, qx*px)                  (gemm-style K-ascending chain)
//   d  = (qn + pn) - 2*c
// ---------------------------------------------------------------------------
__global__ void k_search(const float* __restrict__ xy,
                         const int*   __restrict__ fps,
                         float* __restrict__ out_xy, int write_xy)
{
    int warp = (blockIdx.x * blockDim.x + threadIdx.x) >> 5;
    int lane = threadIdx.x & 31;
    if (warp >= NQ) return;
    int b = warp / SSZ;
    const float2* xyb = reinterpret_cast<const float2*>(xy) + (size_t)b * NN;

    int fi = fps[warp];
    float2 q = xyb[fi];
    float qn = __fadd_rn(__fmul_rn(q.x, q.x), __fmul_rn(q.y, q.y));

    if (write_xy && lane == 0) {
        out_xy[2*warp]     = q.x;
        out_xy[2*warp + 1] = q.y;
    }

    int count = 0;
    int first = -1;
    int* idxp = g_idx + (size_t)warp * KK;

    for (int j0 = 0; j0 < NN; j0 += 32) {
        float2 p = xyb[j0 + lane];
        float pn = __fadd_rn(__fmul_rn(p.x, p.x), __fmul_rn(p.y, p.y));
        float c  = __fmaf_rn(q.y, p.y, __fmul_rn(q.x, p.x));
        float d  = __fsub_rn(__fadd_rn(qn, pn), __fmul_rn(2.0f, c));
        bool hit = !(d > R2);                 // included iff d <= R^2
        unsigned m = __ballot_sync(0xffffffffu, hit);
        if (m) {
            if (first < 0) first = j0 + (__ffs(m) - 1);
            int pos = count + __popc(m & ((1u << lane) - 1u));
            if (hit && pos < KK) idxp[pos] = j0 + lane;
            count += __popc(m);
            if (count >= KK) break;
        }
    }
    if (count < KK) {
        if (first < 0) first = NN - 1;        // unreachable (self always hits)
        for (int pos = count + lane; pos < KK; pos += 32) idxp[pos] = first;
    }
}

// ---------------------------------------------------------------------------
// K2: per-query stats. Block per query, 256 thr = 64 channels x 4 k-chunks.
// Gathers g[k][c] (events for c<62, xy for c>=62), per-channel mean over 64
// samples, and SS_c = sumsq - sum*mean, reduced over channels -> g_ss[q].
// All reductions fixed-order (deterministic).
// ---------------------------------------------------------------------------
__global__ void k_stats(const float* __restrict__ xy,
                        const float* __restrict__ ev)
{
    int q = blockIdx.x;
    int b = q / SSZ;
    int t = threadIdx.x;
    int c = t & 63, kk = t >> 6;

    __shared__ int   sidx[KK];
    __shared__ float ssum[256];
    __shared__ float ssq[256];

    if (t < KK) sidx[t] = g_idx[(size_t)q*KK + t];
    __syncthreads();

    const float* evb = ev + (size_t)b * NN * DD;
    const float* xyb = xy + (size_t)b * NN * 2;

    float s1 = 0.f, s2 = 0.f;
    #pragma unroll
    for (int ki = 0; ki < 16; ki++) {
        int k = kk * 16 + ki;
        int j = sidx[k];
        float v = (c < DD) ? __ldg(evb + (size_t)j * DD + c)
                           : __ldg(xyb + (size_t)j * 2 + (c - DD));
        s1 += v;
        s2 = fmaf(v, v, s2);
    }
    ssum[t] = s1; ssq[t] = s2;
    __syncthreads();

    if (t < 64) {
        float tot = ((ssum[t] + ssum[t+64]) + ssum[t+128]) + ssum[t+192];
        float tq  = ((ssq[t]  + ssq[t+64])  + ssq[t+128])  + ssq[t+192];
        float mean = tot * (1.0f / 64.0f);
        g_mean[(size_t)q*CC + t] = mean;
        ssum[t] = tq - tot * mean;            // SS for this channel
    }
    __syncthreads();
    // fixed-order tree reduce 64 -> 1
    if (t < 32) ssum[t] += ssum[t+32]; __syncthreads();
    if (t < 16) ssum[t] += ssum[t+16]; __syncthreads();
    if (t <  8) ssum[t] += ssum[t+8];  __syncthreads();
    if (t <  4) ssum[t] += ssum[t+4];  __syncthreads();
    if (t <  2) ssum[t] += ssum[t+2];  __syncthreads();
    if (t == 0) g_ss[q] = ssum[0] + ssum[1];
}

// ---------------------------------------------------------------------------
// K3: reduce per-query SS -> per-batch std -> rstd. One block, fixed order.
// ---------------------------------------------------------------------------
__global__ void k_finalize()
{
    __shared__ float sh[256];
    int t = threadIdx.x;
    for (int b = 0; b < BB; b++) {
        float s = 0.f;
        #pragma unroll
        for (int i = 0; i < 8; i++) s += g_ss[(size_t)b*SSZ + t*8 + i];
        sh[t] = s;
        __syncthreads();
        for (int off = 128; off >= 1; off >>= 1) {
            if (t < off) sh[t] += sh[t + off];
            __syncthreads();
        }
        if (t == 0) {
            float var = sh[0] / (float)(MMM - 1);  // ddof=1
            float sd  = sqrtf(var);
            g_rstd[b] = 1.0f / (sd + 1e-5f);
        }
        __syncthreads();
    }
}

// ---------------------------------------------------------------------------
// K4: regather + normalize + affine, write new_events (B,S,64,64).
// Block per query, thread (c = t&63, kk = t>>6), k strided by 4 -> coalesced
// 64-float rows per k.
// ---------------------------------------------------------------------------
__global__ void k_write(const float* __restrict__ xy,
                        const float* __restrict__ ev,
                        const float* __restrict__ alpha,
                        const float* __restrict__ beta,
                        float* __restrict__ out_ev)
{
    int q = blockIdx.x;
    int b = q / SSZ;
    int t = threadIdx.x;
    int c = t & 63, kk = t >> 6;

    __shared__ int   sidx[KK];
    __shared__ float smean[CC];
    __shared__ float sal[CC];
    __shared__ float sbe[CC];

    if (t < KK)               sidx[t]        = g_idx[(size_t)q*KK + t];
    else if (t < 128)         smean[t - 64]  = g_mean[(size_t)q*CC + (t - 64)];
    else if (t < 192)         sal[t - 128]   = alpha[t - 128];
    else                      sbe[t - 192]   = beta[t - 192];
    __syncthreads();

    float rstd = g_rstd[b];
    float mean = smean[c];
    float al   = sal[c];
    float be   = sbe[c];

    const float* evb = ev + (size_t)b * NN * DD;
    const float* xyb = xy + (size_t)b * NN * 2;
    float* op = out_ev + (size_t)q * KK * CC;

    #pragma unroll
    for (int k = kk; k < KK; k += 4) {
        int j = sidx[k];
        float v = (c < DD) ? __ldg(evb + (size_t)j * DD + c)
                           : __ldg(xyb + (size_t)j * 2 + (c - DD));
        float g = (v - mean) * rstd;
        op[(size_t)k * CC + c] = al * g + be;
    }
}

// ---------------------------------------------------------------------------
extern "C" void kernel_launch(void* const* d_in, const int* in_sizes, int n_in,
                              void* d_out, int out_size)
{
    const float* xy    = (const float*)d_in[0];
    const float* ev    = (const float*)d_in[1];
    const int*   fps   = (const int*)d_in[2];
    const float* alpha = (const float*)d_in[3];
    const float* beta  = (const float*)d_in[4];
    float* out = (float*)d_out;

    long long ev_elems = (long long)NQ * KK * CC;      // 33,554,432
    int has_xy = ((long long)out_size >= ev_elems + (long long)NQ * 2) ? 1 : 0;
    float* out_ev = out + (has_xy ? NQ * 2 : 0);

    k_search  <<<NQ/8, 256>>>(xy, fps, out, has_xy);
    k_stats   <<<NQ,   256>>>(xy, ev);
    k_finalize<<<1,    256>>>();
    k_write   <<<NQ,   256>>>(xy, ev, alpha, beta, out_ev);
}

// round 2
// speedup vs baseline: 1.2866x; 1.2866x over previous
#include <cuda_runtime.h>

#define BB 4
#define NN 16384
#define SSZ 2048            // queries per batch (NEVENT)
#define DD 62
#define CC 64               // D + 2
#define KK 64               // NSAMPLE
#define NQ (BB*SSZ)         // 8192 total queries
#define MMM 8388608         // SSZ*KK*CC per batch
#define R2 0.01f

// ---- scratch (device globals; fully overwritten every launch) ----
__device__ int   g_idx[NQ*KK];     // neighbor indices
__device__ float g_mean[NQ*CC];    // per-(query,channel) means
__device__ float g_ss[NQ];         // per-query sum of squared centered
__device__ float g_rstd[BB];       // 1/(std+1e-5) per batch

// ---------------------------------------------------------------------------
// K_A: fused ball-query + per-query stats. One block (256 thr) per query.
//
// Search: cooperative ordered compaction, 256 candidates/iter, early exit
// after 64 hits. Distance replicates reference fp32 op sequence exactly:
//   qn = qx*qx + qy*qy ; pn = px*px + py*py   (mul,mul,add — no contraction)
//   c  = fma(qy,py, qx*px)                    (einsum K-ascending chain)
//   d  = (qn + pn) - 2*c ;  hit iff !(d > R^2)
//
// Stats: float2 gather (event rows are 248B -> 8B aligned), per-channel mean
// + SS via sumsq - sum*mean, fixed-order reductions (deterministic).
// ---------------------------------------------------------------------------
__global__ __launch_bounds__(256) void k_search_stats(
    const float* __restrict__ xy, const float* __restrict__ ev,
    const int* __restrict__ fps, float* __restrict__ out_xy, int write_xy)
{
    int q = blockIdx.x;
    int b = q >> 11;                 // q / SSZ
    int t = threadIdx.x;
    int wid = t >> 5, lane = t & 31;

    __shared__ int      sidx[KK];
    __shared__ unsigned wmask[8];
    __shared__ float2   ssum2[256];
    __shared__ float2   ssq2[256];

    const float2* xyb = reinterpret_cast<const float2*>(xy) + (size_t)b * NN;

    int fi = fps[q];
    float2 qp = xyb[fi];
    float qn = __fadd_rn(__fmul_rn(qp.x, qp.x), __fmul_rn(qp.y, qp.y));
    if (write_xy && t == 0) { out_xy[2*q] = qp.x; out_xy[2*q+1] = qp.y; }

    // ---- search ----
    int count = 0;                    // replicated, consistent across threads
    unsigned lmask = (1u << lane) - 1u;
    for (int j0 = 0; j0 < NN; j0 += 256) {
        int j = j0 + t;
        float2 p = xyb[j];
        float pn = __fadd_rn(__fmul_rn(p.x, p.x), __fmul_rn(p.y, p.y));
        float cc = __fmaf_rn(qp.y, p.y, __fmul_rn(qp.x, p.x));
        float d  = __fsub_rn(__fadd_rn(qn, pn), __fmul_rn(2.0f, cc));
        bool hit = !(d > R2);
        unsigned m = __ballot_sync(0xffffffffu, hit);
        if (lane == 0) wmask[wid] = m;
        __syncthreads();
        int base = count, tot = 0;
        #pragma unroll
        for (int w = 0; w < 8; w++) {
            int pc = __popc(wmask[w]);
            if (w < wid) base += pc;
            tot += pc;
        }
        if (hit) {
            int pos = base + __popc(m & lmask);
            if (pos < KK) sidx[pos] = j;
        }
        count += tot;
        if (count >= KK) break;
        __syncthreads();              // protect wmask for next iteration
    }
    __syncthreads();                  // sidx writes visible
    // pad with first hit (count >= 1 always: query point itself has d == 0)
    for (int pos = count + t; pos < KK; pos += 256) sidx[pos] = sidx[0];
    __syncthreads();
    if (t < KK) g_idx[(size_t)q * KK + t] = sidx[t];

    // ---- stats: thread (c2 = t&31 channel-pair, kg = t>>5 k-group) ----
    int c2 = t & 31, kg = t >> 5;
    const float* evb = ev + (size_t)b * NN * DD;
    float2 s1 = make_float2(0.f, 0.f), s2 = make_float2(0.f, 0.f);
    #pragma unroll
    for (int ki = 0; ki < 8; ki++) {
        int k = kg * 8 + ki;
        int j = sidx[k];
        float2 v = (c2 < 31)
            ? reinterpret_cast<const float2*>(evb + (size_t)j * DD)[c2]
            : xyb[j];
        s1.x += v.x; s1.y += v.y;
        s2.x = fmaf(v.x, v.x, s2.x);
        s2.y = fmaf(v.y, v.y, s2.y);
    }
    ssum2[t] = s1; ssq2[t] = s2;
    __syncthreads();

    if (t < 32) {
        float2 tot = ssum2[t], tq = ssq2[t];
        #pragma unroll
        for (int w = 1; w < 8; w++) {
            float2 a = ssum2[t + w*32]; tot.x += a.x; tot.y += a.y;
            float2 c = ssq2[t + w*32];  tq.x  += c.x; tq.y  += c.y;
        }
        float2 mean = make_float2(tot.x * (1.0f/64.0f), tot.y * (1.0f/64.0f));
        reinterpret_cast<float2*>(g_mean)[(size_t)q * 32 + t] = mean;
        float ss = (tq.x - tot.x * mean.x) + (tq.y - tot.y * mean.y);
        // fixed-order warp tree reduction (deterministic)
        ss += __shfl_down_sync(0xffffffffu, ss, 16);
        ss += __shfl_down_sync(0xffffffffu, ss, 8);
        ss += __shfl_down_sync(0xffffffffu, ss, 4);
        ss += __shfl_down_sync(0xffffffffu, ss, 2);
        ss += __shfl_down_sync(0xffffffffu, ss, 1);
        if (t == 0) g_ss[q] = ss;
    }
}

// ---------------------------------------------------------------------------
// K_B: per-batch SS reduce -> rstd. One block per batch, fixed-order tree.
// ---------------------------------------------------------------------------
__global__ __launch_bounds__(256) void k_finalize()
{
    int b = blockIdx.x, t = threadIdx.x;
    __shared__ float sh[256];
    float s = 0.f;
    #pragma unroll
    for (int i = 0; i < 8; i++) s += g_ss[(size_t)b * SSZ + t*8 + i];
    sh[t] = s;
    __syncthreads();
    for (int off = 128; off >= 1; off >>= 1) {
        if (t < off) sh[t] += sh[t + off];
        __syncthreads();
    }
    if (t == 0) {
        float var = sh[0] / (float)(MMM - 1);   // ddof = 1
        g_rstd[b] = 1.0f / (sqrtf(var) + 1e-5f);
    }
}

// ---------------------------------------------------------------------------
// K_C: regather + normalize + affine, float2 throughout.
// Block per query; thread (c2 = t&31, kg = t>>5); warp covers one 256B row.
// ---------------------------------------------------------------------------
__global__ __launch_bounds__(256) void k_write(
    const float* __restrict__ xy, const float* __restrict__ ev,
    const float* __restrict__ alpha, const float* __restrict__ beta,
    float* __restrict__ out_ev)
{
    int q = blockIdx.x;
    int b = q >> 11;
    int t = threadIdx.x;
    int c2 = t & 31, kg = t >> 5;

    __shared__ int    sidx[KK];
    __shared__ float2 smean[32], sal[32], sbe[32];

    if (t < 64)        sidx[t]      = g_idx[(size_t)q * KK + t];
    else if (t < 96)   smean[t-64]  = reinterpret_cast<const float2*>(g_mean)[(size_t)q * 32 + (t-64)];
    else if (t < 128)  sal[t-96]    = reinterpret_cast<const float2*>(alpha)[t-96];
    else if (t < 160)  sbe[t-128]   = reinterpret_cast<const float2*>(beta)[t-128];
    __syncthreads();

    float  rstd = g_rstd[b];
    float2 mean = smean[c2];
    float2 al   = sal[c2];
    float2 be   = sbe[c2];

    const float*  evb = ev + (size_t)b * NN * DD;
    const float2* xyb = reinterpret_cast<const float2*>(xy) + (size_t)b * NN;
    float2* op = reinterpret_cast<float2*>(out_ev) + (size_t)q * KK * 32;

    #pragma unroll
    for (int ki = 0; ki < 8; ki++) {
        int k = kg * 8 + ki;
        int j = sidx[k];
        float2 v = (c2 < 31)
            ? reinterpret_cast<const float2*>(evb + (size_t)j * DD)[c2]
            : xyb[j];
        float2 r;
        r.x = fmaf(al.x, (v.x - mean.x) * rstd, be.x);
        r.y = fmaf(al.y, (v.y - mean.y) * rstd, be.y);
        op[(size_t)k * 32 + c2] = r;
    }
}

// ---------------------------------------------------------------------------
extern "C" void kernel_launch(void* const* d_in, const int* in_sizes, int n_in,
                              void* d_out, int out_size)
{
    const float* xy    = (const float*)d_in[0];
    const float* ev    = (const float*)d_in[1];
    const int*   fps   = (const int*)d_in[2];
    const float* alpha = (const float*)d_in[3];
    const float* beta  = (const float*)d_in[4];
    float* out = (float*)d_out;

    long long ev_elems = (long long)NQ * KK * CC;
    int has_xy = ((long long)out_size >= ev_elems + (long long)NQ * 2) ? 1 : 0;
    float* out_ev = out + (has_xy ? NQ * 2 : 0);

    k_search_stats<<<NQ, 256>>>(xy, ev, fps, out, has_xy);
    k_finalize    <<<BB, 256>>>();
    k_write       <<<NQ, 256>>>(xy, ev, alpha, beta, out_ev);
}

// round 4
// speedup vs baseline: 1.4778x; 1.1486x over previous
#include <cuda_runtime.h>

#define BB 4
#define NN 16384
#define SSZ 2048            // queries per batch (NEVENT)
#define DD 62
#define CC 64               // D + 2
#define KK 64               // NSAMPLE
#define NQ (BB*SSZ)         // 8192 total queries
#define MMM 8388608         // SSZ*KK*CC per batch
#define R2 0.01f

// ---- scratch (device globals; fully overwritten every launch) ----
__device__ int    g_idx[NQ*KK];     // neighbor indices
__device__ float4 g_mean4[NQ*16];   // per-(query,channel) means (64 ch = 16 float4)
__device__ float  g_ss[NQ];         // per-query sum of squared centered
__device__ float  g_rstd[BB];       // 1/(std+1e-5) per batch

// ---------------------------------------------------------------------------
// K_A: fused ball-query + stats, WARP-per-query. 8 queries per 256-thr block.
// No __syncthreads anywhere — each warp is fully independent.
//
// Search: 2 points per lane per iter (float4 load = 64 candidates/warp-iter),
// ordered compaction via 2 ballots + popc prefix; early exit at 64 hits.
// Distance replicates reference fp32 op sequence exactly:
//   qn = qx*qx + qy*qy ; pn = px*px + py*py   (mul,mul,add — no contraction)
//   c  = fma(qy,py, qx*px)                    (einsum K-ascending chain)
//   d  = (qn + pn) - 2*c ;  hit iff !(d > R^2)
//
// Stats: lane = channel-pair (c2), k-loop over 64 samples; per-lane mean,
// SS via sumsq - sum*mean, one shfl tree (fixed order, deterministic).
// ---------------------------------------------------------------------------
__global__ __launch_bounds__(256) void k_search_stats(
    const float* __restrict__ xy, const float* __restrict__ ev,
    const int* __restrict__ fps, float* __restrict__ out_xy, int write_xy)
{
    int w    = threadIdx.x >> 5;
    int lane = threadIdx.x & 31;
    int q    = blockIdx.x * 8 + w;
    int b    = q >> 11;                       // q / SSZ

    __shared__ int sidx[8][KK];

    const float2* xyb  = reinterpret_cast<const float2*>(xy) + (size_t)b * NN;
    const float4* xyb4 = reinterpret_cast<const float4*>(xyb);

    int fi = fps[q];
    float2 qp = xyb[fi];
    float qn = __fadd_rn(__fmul_rn(qp.x, qp.x), __fmul_rn(qp.y, qp.y));
    if (write_xy && lane == 0) { out_xy[2*q] = qp.x; out_xy[2*q+1] = qp.y; }

    // ---- search: 64 candidates per iteration ----
    unsigned lmask = (1u << lane) - 1u;
    int count = 0;                            // uniform across warp
    for (int j0 = 0; j0 < NN; j0 += 64) {
        float4 f = xyb4[(j0 >> 1) + lane];    // points j0+2*lane, j0+2*lane+1
        float pn0 = __fadd_rn(__fmul_rn(f.x, f.x), __fmul_rn(f.y, f.y));
        float c0  = __fmaf_rn(qp.y, f.y, __fmul_rn(qp.x, f.x));
        float d0  = __fsub_rn(__fadd_rn(qn, pn0), __fmul_rn(2.0f, c0));
        bool  h0  = !(d0 > R2);
        float pn1 = __fadd_rn(__fmul_rn(f.z, f.z), __fmul_rn(f.w, f.w));
        float c1  = __fmaf_rn(qp.y, f.w, __fmul_rn(qp.x, f.z));
        float d1  = __fsub_rn(__fadd_rn(qn, pn1), __fmul_rn(2.0f, c1));
        bool  h1  = !(d1 > R2);

        unsigned m0 = __ballot_sync(0xffffffffu, h0);
        unsigned m1 = __ballot_sync(0xffffffffu, h1);
        int before = __popc(m0 & lmask) + __popc(m1 & lmask);
        int pos0 = count + before;
        if (h0 && pos0 < KK) sidx[w][pos0] = j0 + 2*lane;
        int pos1 = pos0 + (h0 ? 1 : 0);
        if (h1 && pos1 < KK) sidx[w][pos1] = j0 + 2*lane + 1;
        count += __popc(m0) + __popc(m1);
        if (count >= KK) break;
    }
    __syncwarp();
    if (count < KK) {                          // pad with first hit (count>=1: self)
        int f0 = sidx[w][0];
        for (int pos = count + lane; pos < KK; pos += 32) sidx[w][pos] = f0;
        __syncwarp();
    }

    // persist indices for k_write (coalesced 256B per warp)
    g_idx[(size_t)q * KK + lane]      = sidx[w][lane];
    g_idx[(size_t)q * KK + lane + 32] = sidx[w][lane + 32];

    // ---- stats: lane = channel pair c2 (0..31) ----
    const float2* evb2 = reinterpret_cast<const float2*>(ev + (size_t)b * NN * DD);
    int c2 = lane;
    float2 s1 = make_float2(0.f, 0.f), s2 = make_float2(0.f, 0.f);
    #pragma unroll 8
    for (int k = 0; k < KK; k++) {
        int j = sidx[w][k];                    // LDS broadcast
        float2 v = (c2 < 31) ? evb2[(size_t)j * 31 + c2] : xyb[j];
        s1.x += v.x; s1.y += v.y;
        s2.x = fmaf(v.x, v.x, s2.x);
        s2.y = fmaf(v.y, v.y, s2.y);
    }
    float2 mean = make_float2(s1.x * (1.0f/64.0f), s1.y * (1.0f/64.0f));
    reinterpret_cast<float2*>(g_mean4)[(size_t)q * 32 + c2] = mean;
    float ss = (s2.x - s1.x * mean.x) + (s2.y - s1.y * mean.y);
    ss += __shfl_down_sync(0xffffffffu, ss, 16);
    ss += __shfl_down_sync(0xffffffffu, ss, 8);
    ss += __shfl_down_sync(0xffffffffu, ss, 4);
    ss += __shfl_down_sync(0xffffffffu, ss, 2);
    ss += __shfl_down_sync(0xffffffffu, ss, 1);
    if (lane == 0) g_ss[q] = ss;
}

// ---------------------------------------------------------------------------
// K_B: per-batch SS reduce -> rstd. One block per batch, fixed-order tree.
// ---------------------------------------------------------------------------
__global__ __launch_bounds__(256) void k_finalize()
{
    int b = blockIdx.x, t = threadIdx.x;
    __shared__ float sh[256];
    float s = 0.f;
    #pragma unroll
    for (int i = 0; i < 8; i++) s += g_ss[(size_t)b * SSZ + t*8 + i];
    sh[t] = s;
    __syncthreads();
    for (int off = 128; off >= 1; off >>= 1) {
        if (t < off) sh[t] += sh[t + off];
        __syncthreads();
    }
    if (t == 0) {
        float var = sh[0] / (float)(MMM - 1);   // ddof = 1
        g_rstd[b] = 1.0f / (sqrtf(var) + 1e-5f);
    }
}

// ---------------------------------------------------------------------------
// K_C: regather + normalize + affine. Block per query.
// Thread = (c4 = t&15 -> 4 channels, kg = t>>4). Two float2 gathers,
// one float4 store; stores fully coalesced (4KB per unroll step).
// ---------------------------------------------------------------------------
__global__ __launch_bounds__(256) void k_write(
    const float* __restrict__ xy, const float* __restrict__ ev,
    const float* __restrict__ alpha, const float* __restrict__ beta,
    float* __restrict__ out_ev)
{
    int q = blockIdx.x;
    int b = q >> 11;
    int t = threadIdx.x;
    int c4 = t & 15, kg = t >> 4;

    __shared__ int    sidx[KK];
    __shared__ float4 smean[16], sal[16], sbe[16];

    if (t < 64)        sidx[t]     = g_idx[(size_t)q * KK + t];
    else if (t < 80)   smean[t-64] = g_mean4[(size_t)q * 16 + (t-64)];
    else if (t < 96)   sal[t-80]   = reinterpret_cast<const float4*>(alpha)[t-80];
    else if (t < 112)  sbe[t-96]   = reinterpret_cast<const float4*>(beta)[t-96];
    __syncthreads();

    float  rstd = g_rstd[b];
    float4 mean = smean[c4];
    float4 al   = sal[c4];
    float4 be   = sbe[c4];

    const float2* evb2 = reinterpret_cast<const float2*>(ev + (size_t)b * NN * DD);
    const float2* xyb  = reinterpret_cast<const float2*>(xy) + (size_t)b * NN;
    float4* op = reinterpret_cast<float4*>(out_ev) + (size_t)q * KK * 16;

    #pragma unroll
    for (int ki = 0; ki < 4; ki++) {
        int k = ki * 16 + kg;
        int j = sidx[k];
        float2 va, vb;
        if (c4 < 15) {
            va = evb2[(size_t)j * 31 + 2*c4];
            vb = evb2[(size_t)j * 31 + 2*c4 + 1];
        } else {
            va = evb2[(size_t)j * 31 + 30];    // channels 60,61
            vb = xyb[j];                        // channels 62,63
        }
        float4 r;
        r.x = fmaf(al.x, (va.x - mean.x) * rstd, be.x);
        r.y = fmaf(al.y, (va.y - mean.y) * rstd, be.y);
        r.z = fmaf(al.z, (vb.x - mean.z) * rstd, be.z);
        r.w = fmaf(al.w, (vb.y - mean.w) * rstd, be.w);
        op[(size_t)k * 16 + c4] = r;
    }
}

// ---------------------------------------------------------------------------
extern "C" void kernel_launch(void* const* d_in, const int* in_sizes, int n_in,
                              void* d_out, int out_size)
{
    const float* xy    = (const float*)d_in[0];
    const float* ev    = (const float*)d_in[1];
    const int*   fps   = (const int*)d_in[2];
    const float* alpha = (const float*)d_in[3];
    const float* beta  = (const float*)d_in[4];
    float* out = (float*)d_out;

    long long ev_elems = (long long)NQ * KK * CC;
    int has_xy = ((long long)out_size >= ev_elems + (long long)NQ * 2) ? 1 : 0;
    float* out_ev = out + (has_xy ? NQ * 2 : 0);

    k_search_stats<<<NQ/8, 256>>>(xy, ev, fps, out, has_xy);
    k_finalize    <<<BB,   256>>>();
    k_write       <<<NQ,   256>>>(xy, ev, alpha, beta, out_ev);
}

// round 5
// speedup vs baseline: 1.5513x; 1.0498x over previous
#include <cuda_runtime.h>

#define BB 4
#define NN 16384
#define SSZ 2048            // queries per batch (NEVENT)
#define DD 62
#define CC 64               // D + 2
#define KK 64               // NSAMPLE
#define NQ (BB*SSZ)         // 8192 total queries
#define MMM 8388608         // SSZ*KK*CC per batch
#define R2 0.01f

// ---- scratch (device globals; fully overwritten every launch) ----
__device__ int    g_idx[NQ*KK];     // neighbor indices
__device__ float4 g_mean4[NQ*16];   // per-(query,channel) means (64 ch = 16 float4)
__device__ float  g_ss[NQ];         // per-query sum of squared centered
__device__ float  g_rstd[BB];       // 1/(std+1e-5) per batch

// ---------------------------------------------------------------------------
// K_A: fused ball-query + stats, WARP-per-query. 4 warps (128 thr) per block.
//
// Search: 4 points per lane per iter (2x float4 = 128 candidates/warp-iter),
// software-pipelined: next chunk's loads issue BEFORE this chunk's ballot
// chain, hiding L1 latency behind the compaction tail. Ordered compaction via
// 4 ballots + popc prefix (index order = (lane, sub) lexicographic = global
// ascending). Early exit at 64 hits.
// Distance replicates reference fp32 op sequence exactly:
//   qn = qx*qx + qy*qy ; pn = px*px + py*py   (mul,mul,add — no contraction)
//   c  = fma(qy,py, qx*px)                    (einsum K-ascending chain)
//   d  = (qn + pn) - 2*c ;  hit iff !(d > R^2)
//
// Stats: lane = channel-pair (c2), k-loop over 64 samples (warp reads one
// coalesced 256B row per step); per-lane mean, SS via sumsq - sum*mean,
// one fixed-order shfl tree (deterministic). No __syncthreads anywhere.
// ---------------------------------------------------------------------------
__global__ __launch_bounds__(128) void k_search_stats(
    const float* __restrict__ xy, const float* __restrict__ ev,
    const int* __restrict__ fps, float* __restrict__ out_xy, int write_xy)
{
    int w    = threadIdx.x >> 5;
    int lane = threadIdx.x & 31;
    int q    = blockIdx.x * 4 + w;
    int b    = q >> 11;                       // q / SSZ

    __shared__ int sidx[4][KK];

    const float2* xyb  = reinterpret_cast<const float2*>(xy) + (size_t)b * NN;
    const float4* xyb4 = reinterpret_cast<const float4*>(xyb);

    int fi = fps[q];
    float2 qp = xyb[fi];
    float qn = __fadd_rn(__fmul_rn(qp.x, qp.x), __fmul_rn(qp.y, qp.y));
    if (write_xy && lane == 0) { out_xy[2*q] = qp.x; out_xy[2*q+1] = qp.y; }

    // ---- search: 128 candidates per iteration, pipelined loads ----
    unsigned lmask = (1u << lane) - 1u;
    int count = 0;                            // uniform across warp
    float4 fa = xyb4[2*lane];                 // points 4*lane+0,1
    float4 fb = xyb4[2*lane + 1];             // points 4*lane+2,3
    for (int j0 = 0; ; j0 += 128) {
        int jn = j0 + 128;
        bool more = (jn < NN);
        float4 na, nb;                        // prefetch next chunk (issues early)
        if (more) {
            na = xyb4[(jn >> 1) + 2*lane];
            nb = xyb4[(jn >> 1) + 2*lane + 1];
        }

        float pn0 = __fadd_rn(__fmul_rn(fa.x, fa.x), __fmul_rn(fa.y, fa.y));
        float c0  = __fmaf_rn(qp.y, fa.y, __fmul_rn(qp.x, fa.x));
        float d0  = __fsub_rn(__fadd_rn(qn, pn0), __fmul_rn(2.0f, c0));
        bool  h0  = !(d0 > R2);
        float pn1 = __fadd_rn(__fmul_rn(fa.z, fa.z), __fmul_rn(fa.w, fa.w));
        float c1  = __fmaf_rn(qp.y, fa.w, __fmul_rn(qp.x, fa.z));
        float d1  = __fsub_rn(__fadd_rn(qn, pn1), __fmul_rn(2.0f, c1));
        bool  h1  = !(d1 > R2);
        float pn2 = __fadd_rn(__fmul_rn(fb.x, fb.x), __fmul_rn(fb.y, fb.y));
        float c2c = __fmaf_rn(qp.y, fb.y, __fmul_rn(qp.x, fb.x));
        float d2  = __fsub_rn(__fadd_rn(qn, pn2), __fmul_rn(2.0f, c2c));
        bool  h2  = !(d2 > R2);
        float pn3 = __fadd_rn(__fmul_rn(fb.z, fb.z), __fmul_rn(fb.w, fb.w));
        float c3  = __fmaf_rn(qp.y, fb.w, __fmul_rn(qp.x, fb.z));
        float d3  = __fsub_rn(__fadd_rn(qn, pn3), __fmul_rn(2.0f, c3));
        bool  h3  = !(d3 > R2);

        unsigned m0 = __ballot_sync(0xffffffffu, h0);
        unsigned m1 = __ballot_sync(0xffffffffu, h1);
        unsigned m2 = __ballot_sync(0xffffffffu, h2);
        unsigned m3 = __ballot_sync(0xffffffffu, h3);

        int before = __popc(m0 & lmask) + __popc(m1 & lmask)
                   + __popc(m2 & lmask) + __popc(m3 & lmask);
        int pos  = count + before;
        int base = j0 + 4*lane;
        if (h0 && pos < KK) sidx[w][pos] = base;
        pos += h0 ? 1 : 0;
        if (h1 && pos < KK) sidx[w][pos] = base + 1;
        pos += h1 ? 1 : 0;
        if (h2 && pos < KK) sidx[w][pos] = base + 2;
        pos += h2 ? 1 : 0;
        if (h3 && pos < KK) sidx[w][pos] = base + 3;

        count += __popc(m0) + __popc(m1) + __popc(m2) + __popc(m3);
        if (count >= KK || !more) break;
        fa = na; fb = nb;
    }
    __syncwarp();
    if (count < KK) {                          // pad with first hit (count>=1: self)
        int f0 = sidx[w][0];
        for (int pos = count + lane; pos < KK; pos += 32) sidx[w][pos] = f0;
        __syncwarp();
    }

    // persist indices for k_write (coalesced 256B per warp)
    g_idx[(size_t)q * KK + lane]      = sidx[w][lane];
    g_idx[(size_t)q * KK + lane + 32] = sidx[w][lane + 32];

    // ---- stats: lane = channel pair c2 (0..31) ----
    const float2* evb2 = reinterpret_cast<const float2*>(ev + (size_t)b * NN * DD);
    int c2 = lane;
    float2 s1 = make_float2(0.f, 0.f), s2 = make_float2(0.f, 0.f);
    #pragma unroll 16
    for (int k = 0; k < KK; k++) {
        int j = sidx[w][k];                    // LDS broadcast
        float2 v = (c2 < 31) ? evb2[(size_t)j * 31 + c2] : xyb[j];
        s1.x += v.x; s1.y += v.y;
        s2.x = fmaf(v.x, v.x, s2.x);
        s2.y = fmaf(v.y, v.y, s2.y);
    }
    float2 mean = make_float2(s1.x * (1.0f/64.0f), s1.y * (1.0f/64.0f));
    reinterpret_cast<float2*>(g_mean4)[(size_t)q * 32 + c2] = mean;
    float ss = (s2.x - s1.x * mean.x) + (s2.y - s1.y * mean.y);
    ss += __shfl_down_sync(0xffffffffu, ss, 16);
    ss += __shfl_down_sync(0xffffffffu, ss, 8);
    ss += __shfl_down_sync(0xffffffffu, ss, 4);
    ss += __shfl_down_sync(0xffffffffu, ss, 2);
    ss += __shfl_down_sync(0xffffffffu, ss, 1);
    if (lane == 0) g_ss[q] = ss;
}

// ---------------------------------------------------------------------------
// K_B: per-batch SS reduce -> rstd. One block per batch, fixed-order tree.
// ---------------------------------------------------------------------------
__global__ __launch_bounds__(256) void k_finalize()
{
    int b = blockIdx.x, t = threadIdx.x;
    __shared__ float sh[256];
    float s = 0.f;
    #pragma unroll
    for (int i = 0; i < 8; i++) s += g_ss[(size_t)b * SSZ + t*8 + i];
    sh[t] = s;
    __syncthreads();
    for (int off = 128; off >= 1; off >>= 1) {
        if (t < off) sh[t] += sh[t + off];
        __syncthreads();
    }
    if (t == 0) {
        float var = sh[0] / (float)(MMM - 1);   // ddof = 1
        g_rstd[b] = 1.0f / (sqrtf(var) + 1e-5f);
    }
}

// ---------------------------------------------------------------------------
// K_C: regather + normalize + affine. Block per query.
// Thread = (c4 = t&15 -> 4 channels, kg = t>>4). Two float2 gathers,
// one float4 store; stores fully coalesced (4KB per unroll step).
// ---------------------------------------------------------------------------
__global__ __launch_bounds__(256) void k_write(
    const float* __restrict__ xy, const float* __restrict__ ev,
    const float* __restrict__ alpha, const float* __restrict__ beta,
    float* __restrict__ out_ev)
{
    int q = blockIdx.x;
    int b = q >> 11;
    int t = threadIdx.x;
    int c4 = t & 15, kg = t >> 4;

    __shared__ int    sidx[KK];
    __shared__ float4 smean[16], sal[16], sbe[16];

    if (t < 64)        sidx[t]     = g_idx[(size_t)q * KK + t];
    else if (t < 80)   smean[t-64] = g_mean4[(size_t)q * 16 + (t-64)];
    else if (t < 96)   sal[t-80]   = reinterpret_cast<const float4*>(alpha)[t-80];
    else if (t < 112)  sbe[t-96]   = reinterpret_cast<const float4*>(beta)[t-96];
    __syncthreads();

    float  rstd = g_rstd[b];
    float4 mean = smean[c4];
    float4 al   = sal[c4];
    float4 be   = sbe[c4];

    const float2* evb2 = reinterpret_cast<const float2*>(ev + (size_t)b * NN * DD);
    const float2* xyb  = reinterpret_cast<const float2*>(xy) + (size_t)b * NN;
    float4* op = reinterpret_cast<float4*>(out_ev) + (size_t)q * KK * 16;

    #pragma unroll
    for (int ki = 0; ki < 4; ki++) {
        int k = ki * 16 + kg;
        int j = sidx[k];
        float2 va, vb;
        if (c4 < 15) {
            va = evb2[(size_t)j * 31 + 2*c4];
            vb = evb2[(size_t)j * 31 + 2*c4 + 1];
        } else {
            va = evb2[(size_t)j * 31 + 30];    // channels 60,61
            vb = xyb[j];                        // channels 62,63
        }
        float4 r;
        r.x = fmaf(al.x, (va.x - mean.x) * rstd, be.x);
        r.y = fmaf(al.y, (va.y - mean.y) * rstd, be.y);
        r.z = fmaf(al.z, (vb.x - mean.z) * rstd, be.z);
        r.w = fmaf(al.w, (vb.y - mean.w) * rstd, be.w);
        op[(size_t)k * 16 + c4] = r;
    }
}

// ---------------------------------------------------------------------------
extern "C" void kernel_launch(void* const* d_in, const int* in_sizes, int n_in,
                              void* d_out, int out_size)
{
    const float* xy    = (const float*)d_in[0];
    const float* ev    = (const float*)d_in[1];
    const int*   fps   = (const int*)d_in[2];
    const float* alpha = (const float*)d_in[3];
    const float* beta  = (const float*)d_in[4];
    float* out = (float*)d_out;

    long long ev_elems = (long long)NQ * KK * CC;
    int has_xy = ((long long)out_size >= ev_elems + (long long)NQ * 2) ? 1 : 0;
    float* out_ev = out + (has_xy ? NQ * 2 : 0);

    k_search_stats<<<NQ/4, 128>>>(xy, ev, fps, out, has_xy);
    k_finalize    <<<BB,   256>>>();
    k_write       <<<NQ,   256>>>(xy, ev, alpha, beta, out_ev);
}

// round 6
// speedup vs baseline: 1.5883x; 1.0239x over previous
#include <cuda_runtime.h>

#define BB 4
#define NN 16384
#define SSZ 2048            // queries per batch (NEVENT)
#define DD 62
#define CC 64               // D + 2
#define KK 64               // NSAMPLE
#define NQ (BB*SSZ)         // 8192 total queries
#define MMM 8388608         // SSZ*KK*CC per batch
#define R2 0.01f

// ---- scratch (device globals; fully overwritten every launch) ----
__device__ int    g_idx[NQ*KK];     // neighbor indices
__device__ float4 g_mean4[NQ*16];   // per-(query,channel) means (64 ch = 16 float4)
__device__ float  g_ss[NQ];         // per-query sum of squared centered
__device__ float  g_rstd[BB];       // 1/(std+1e-5) per batch

// ---------------------------------------------------------------------------
// K_A: fused ball-query + stats. TWO queries per warp sharing one candidate
// stream: one float4-pair load + one set of |p|^2 per chunk feeds two
// independent ballot/compaction chains (the ballot chain is the critical
// path; two chains double retirement per iteration). Early exit when both
// queries have 64 hits. Warp-uniform done-flags keep ballots convergent.
//
// Distance replicates reference fp32 op sequence exactly:
//   qn = qx*qx + qy*qy ; pn = px*px + py*py   (mul,mul,add — no contraction)
//   c  = fma(qy,py, qx*px)                    (einsum K-ascending chain)
//   d  = (qn + pn) - 2*c ;  hit iff !(d > R^2)
//
// Stats: both queries interleaved in one k-loop (2x gather MLP); lane =
// channel-pair; per-lane mean, SS via sumsq - sum*mean; fixed-order shfl
// trees (deterministic). No __syncthreads anywhere.
// ---------------------------------------------------------------------------
__global__ __launch_bounds__(128) void k_search_stats(
    const float* __restrict__ xy, const float* __restrict__ ev,
    const int* __restrict__ fps, float* __restrict__ out_xy, int write_xy)
{
    int w    = threadIdx.x >> 5;
    int lane = threadIdx.x & 31;
    int q0   = blockIdx.x * 8 + w * 2;        // this warp's two queries
    int q1   = q0 + 1;
    int b    = q0 >> 11;                      // same batch for both

    __shared__ int sidx[4][2][KK];

    const float2* xyb  = reinterpret_cast<const float2*>(xy) + (size_t)b * NN;
    const float4* xyb4 = reinterpret_cast<const float4*>(xyb);

    float2 qa = xyb[fps[q0]];
    float2 qb = xyb[fps[q1]];
    float qna = __fadd_rn(__fmul_rn(qa.x, qa.x), __fmul_rn(qa.y, qa.y));
    float qnb = __fadd_rn(__fmul_rn(qb.x, qb.x), __fmul_rn(qb.y, qb.y));
    if (write_xy && lane == 0) {
        out_xy[2*q0] = qa.x; out_xy[2*q0+1] = qa.y;
        out_xy[2*q1] = qb.x; out_xy[2*q1+1] = qb.y;
    }

    // ---- search: 128 candidates/iter shared by both queries ----
    unsigned lmask = (1u << lane) - 1u;
    int cnt0 = 0, cnt1 = 0;                   // warp-uniform
    float4 fa = xyb4[2*lane];                 // points 4*lane+0,1
    float4 fb = xyb4[2*lane + 1];             // points 4*lane+2,3
    for (int j0 = 0; ; j0 += 128) {
        int jn = j0 + 128;
        bool more = (jn < NN);
        float4 na, nb;                        // prefetch next chunk
        if (more) {
            na = xyb4[(jn >> 1) + 2*lane];
            nb = xyb4[(jn >> 1) + 2*lane + 1];
        }
        // |p|^2 shared between the two queries
        float pn0 = __fadd_rn(__fmul_rn(fa.x, fa.x), __fmul_rn(fa.y, fa.y));
        float pn1 = __fadd_rn(__fmul_rn(fa.z, fa.z), __fmul_rn(fa.w, fa.w));
        float pn2 = __fadd_rn(__fmul_rn(fb.x, fb.x), __fmul_rn(fb.y, fb.y));
        float pn3 = __fadd_rn(__fmul_rn(fb.z, fb.z), __fmul_rn(fb.w, fb.w));
        int base = j0 + 4*lane;

        if (cnt0 < KK) {                       // uniform branch: chain for q0
            float c0 = __fmaf_rn(qa.y, fa.y, __fmul_rn(qa.x, fa.x));
            float c1 = __fmaf_rn(qa.y, fa.w, __fmul_rn(qa.x, fa.z));
            float c2 = __fmaf_rn(qa.y, fb.y, __fmul_rn(qa.x, fb.x));
            float c3 = __fmaf_rn(qa.y, fb.w, __fmul_rn(qa.x, fb.z));
            bool h0 = !(__fsub_rn(__fadd_rn(qna, pn0), __fmul_rn(2.0f, c0)) > R2);
            bool h1 = !(__fsub_rn(__fadd_rn(qna, pn1), __fmul_rn(2.0f, c1)) > R2);
            bool h2 = !(__fsub_rn(__fadd_rn(qna, pn2), __fmul_rn(2.0f, c2)) > R2);
            bool h3 = !(__fsub_rn(__fadd_rn(qna, pn3), __fmul_rn(2.0f, c3)) > R2);
            unsigned m0 = __ballot_sync(0xffffffffu, h0);
            unsigned m1 = __ballot_sync(0xffffffffu, h1);
            unsigned m2 = __ballot_sync(0xffffffffu, h2);
            unsigned m3 = __ballot_sync(0xffffffffu, h3);
            int pos = cnt0 + __popc(m0 & lmask) + __popc(m1 & lmask)
                           + __popc(m2 & lmask) + __popc(m3 & lmask);
            if (h0 && pos < KK) sidx[w][0][pos] = base;
            pos += h0 ? 1 : 0;
            if (h1 && pos < KK) sidx[w][0][pos] = base + 1;
            pos += h1 ? 1 : 0;
            if (h2 && pos < KK) sidx[w][0][pos] = base + 2;
            pos += h2 ? 1 : 0;
            if (h3 && pos < KK) sidx[w][0][pos] = base + 3;
            cnt0 += __popc(m0) + __popc(m1) + __popc(m2) + __popc(m3);
        }
        if (cnt1 < KK) {                       // uniform branch: chain for q1
            float c0 = __fmaf_rn(qb.y, fa.y, __fmul_rn(qb.x, fa.x));
            float c1 = __fmaf_rn(qb.y, fa.w, __fmul_rn(qb.x, fa.z));
            float c2 = __fmaf_rn(qb.y, fb.y, __fmul_rn(qb.x, fb.x));
            float c3 = __fmaf_rn(qb.y, fb.w, __fmul_rn(qb.x, fb.z));
            bool h0 = !(__fsub_rn(__fadd_rn(qnb, pn0), __fmul_rn(2.0f, c0)) > R2);
            bool h1 = !(__fsub_rn(__fadd_rn(qnb, pn1), __fmul_rn(2.0f, c1)) > R2);
            bool h2 = !(__fsub_rn(__fadd_rn(qnb, pn2), __fmul_rn(2.0f, c2)) > R2);
            bool h3 = !(__fsub_rn(__fadd_rn(qnb, pn3), __fmul_rn(2.0f, c3)) > R2);
            unsigned m0 = __ballot_sync(0xffffffffu, h0);
            unsigned m1 = __ballot_sync(0xffffffffu, h1);
            unsigned m2 = __ballot_sync(0xffffffffu, h2);
            unsigned m3 = __ballot_sync(0xffffffffu, h3);
            int pos = cnt1 + __popc(m0 & lmask) + __popc(m1 & lmask)
                           + __popc(m2 & lmask) + __popc(m3 & lmask);
            if (h0 && pos < KK) sidx[w][1][pos] = base;
            pos += h0 ? 1 : 0;
            if (h1 && pos < KK) sidx[w][1][pos] = base + 1;
            pos += h1 ? 1 : 0;
            if (h2 && pos < KK) sidx[w][1][pos] = base + 2;
            pos += h2 ? 1 : 0;
            if (h3 && pos < KK) sidx[w][1][pos] = base + 3;
            cnt1 += __popc(m0) + __popc(m1) + __popc(m2) + __popc(m3);
        }
        if ((cnt0 >= KK && cnt1 >= KK) || !more) break;
        fa = na; fb = nb;
    }
    __syncwarp();
    if (cnt0 < KK) {                           // pad (cnt>=1 always: self-hit)
        int f0 = sidx[w][0][0];
        for (int pos = cnt0 + lane; pos < KK; pos += 32) sidx[w][0][pos] = f0;
    }
    if (cnt1 < KK) {
        int f0 = sidx[w][1][0];
        for (int pos = cnt1 + lane; pos < KK; pos += 32) sidx[w][1][pos] = f0;
    }
    __syncwarp();

    // persist indices for k_write (coalesced)
    g_idx[(size_t)q0 * KK + lane]      = sidx[w][0][lane];
    g_idx[(size_t)q0 * KK + lane + 32] = sidx[w][0][lane + 32];
    g_idx[(size_t)q1 * KK + lane]      = sidx[w][1][lane];
    g_idx[(size_t)q1 * KK + lane + 32] = sidx[w][1][lane + 32];

    // ---- stats: both queries interleaved (2x MLP); lane = channel pair ----
    const float2* evb2 = reinterpret_cast<const float2*>(ev + (size_t)b * NN * DD);
    float2 s1a = make_float2(0.f,0.f), s2a = make_float2(0.f,0.f);
    float2 s1b = make_float2(0.f,0.f), s2b = make_float2(0.f,0.f);
    bool isxy = (lane == 31);
    #pragma unroll 8
    for (int k = 0; k < KK; k++) {
        int ja = sidx[w][0][k];
        int jb = sidx[w][1][k];
        float2 va = isxy ? xyb[ja] : evb2[(size_t)ja * 31 + lane];
        float2 vb = isxy ? xyb[jb] : evb2[(size_t)jb * 31 + lane];
        s1a.x += va.x; s1a.y += va.y;
        s2a.x = fmaf(va.x, va.x, s2a.x);
        s2a.y = fmaf(va.y, va.y, s2a.y);
        s1b.x += vb.x; s1b.y += vb.y;
        s2b.x = fmaf(vb.x, vb.x, s2b.x);
        s2b.y = fmaf(vb.y, vb.y, s2b.y);
    }
    float2 ma = make_float2(s1a.x * (1.0f/64.0f), s1a.y * (1.0f/64.0f));
    float2 mb = make_float2(s1b.x * (1.0f/64.0f), s1b.y * (1.0f/64.0f));
    reinterpret_cast<float2*>(g_mean4)[(size_t)q0 * 32 + lane] = ma;
    reinterpret_cast<float2*>(g_mean4)[(size_t)q1 * 32 + lane] = mb;
    float ssa = (s2a.x - s1a.x * ma.x) + (s2a.y - s1a.y * ma.y);
    float ssb = (s2b.x - s1b.x * mb.x) + (s2b.y - s1b.y * mb.y);
    #pragma unroll
    for (int off = 16; off >= 1; off >>= 1) {
        ssa += __shfl_down_sync(0xffffffffu, ssa, off);
        ssb += __shfl_down_sync(0xffffffffu, ssb, off);
    }
    if (lane == 0) { g_ss[q0] = ssa; g_ss[q1] = ssb; }
}

// ---------------------------------------------------------------------------
// K_B: per-batch SS reduce -> rstd. One block per batch, fixed-order tree.
// ---------------------------------------------------------------------------
__global__ __launch_bounds__(256) void k_finalize()
{
    int b = blockIdx.x, t = threadIdx.x;
    __shared__ float sh[256];
    float s = 0.f;
    #pragma unroll
    for (int i = 0; i < 8; i++) s += g_ss[(size_t)b * SSZ + t*8 + i];
    sh[t] = s;
    __syncthreads();
    for (int off = 128; off >= 1; off >>= 1) {
        if (t < off) sh[t] += sh[t + off];
        __syncthreads();
    }
    if (t == 0) {
        float var = sh[0] / (float)(MMM - 1);   // ddof = 1
        g_rstd[b] = 1.0f / (sqrtf(var) + 1e-5f);
    }
}

// ---------------------------------------------------------------------------
// K_C: regather + normalize + affine. Block per query.
// Thread = (c4 = t&15 -> 4 channels, kg = t>>4). Two float2 gathers,
// one float4 store; stores fully coalesced (4KB per unroll step).
// ---------------------------------------------------------------------------
__global__ __launch_bounds__(256) void k_write(
    const float* __restrict__ xy, const float* __restrict__ ev,
    const float* __restrict__ alpha, const float* __restrict__ beta,
    float* __restrict__ out_ev)
{
    int q = blockIdx.x;
    int b = q >> 11;
    int t = threadIdx.x;
    int c4 = t & 15, kg = t >> 4;

    __shared__ int    sidx[KK];
    __shared__ float4 smean[16], sal[16], sbe[16];

    if (t < 64)        sidx[t]     = g_idx[(size_t)q * KK + t];
    else if (t < 80)   smean[t-64] = g_mean4[(size_t)q * 16 + (t-64)];
    else if (t < 96)   sal[t-80]   = reinterpret_cast<const float4*>(alpha)[t-80];
    else if (t < 112)  sbe[t-96]   = reinterpret_cast<const float4*>(beta)[t-96];
    __syncthreads();

    float  rstd = g_rstd[b];
    float4 mean = smean[c4];
    float4 al   = sal[c4];
    float4 be   = sbe[c4];

    const float2* evb2 = reinterpret_cast<const float2*>(ev + (size_t)b * NN * DD);
    const float2* xyb  = reinterpret_cast<const float2*>(xy) + (size_t)b * NN;
    float4* op = reinterpret_cast<float4*>(out_ev) + (size_t)q * KK * 16;

    #pragma unroll
    for (int ki = 0; ki < 4; ki++) {
        int k = ki * 16 + kg;
        int j = sidx[k];
        float2 va, vb;
        if (c4 < 15) {
            va = evb2[(size_t)j * 31 + 2*c4];
            vb = evb2[(size_t)j * 31 + 2*c4 + 1];
        } else {
            va = evb2[(size_t)j * 31 + 30];    // channels 60,61
            vb = xyb[j];                        // channels 62,63
        }
        float4 r;
        r.x = fmaf(al.x, (va.x - mean.x) * rstd, be.x);
        r.y = fmaf(al.y, (va.y - mean.y) * rstd, be.y);
        r.z = fmaf(al.z, (vb.x - mean.z) * rstd, be.z);
        r.w = fmaf(al.w, (vb.y - mean.w) * rstd, be.w);
        op[(size_t)k * 16 + c4] = r;
    }
}

// ---------------------------------------------------------------------------
extern "C" void kernel_launch(void* const* d_in, const int* in_sizes, int n_in,
                              void* d_out, int out_size)
{
    const float* xy    = (const float*)d_in[0];
    const float* ev    = (const float*)d_in[1];
    const int*   fps   = (const int*)d_in[2];
    const float* alpha = (const float*)d_in[3];
    const float* beta  = (const float*)d_in[4];
    float* out = (float*)d_out;

    long long ev_elems = (long long)NQ * KK * CC;
    int has_xy = ((long long)out_size >= ev_elems + (long long)NQ * 2) ? 1 : 0;
    float* out_ev = out + (has_xy ? NQ * 2 : 0);

    k_search_stats<<<NQ/8, 128>>>(xy, ev, fps, out, has_xy);
    k_finalize    <<<BB,   256>>>();
    k_write       <<<NQ,   256>>>(xy, ev, alpha, beta, out_ev);
}